// round 14
// baseline (speedup 1.0000x reference)
#include <cuda_runtime.h>
#include <math.h>

// YOLO loss — fused single launch. Warp-level double-buffered cp.async
// pipeline staging pred+tcls+tbox together; compute reads smem only.
// Outputs 5 f32: total, reg, containing, noobj, cls.

#define S_GRID_INV (1.0f / 14.0f)
#define L_COORD 5.0f
#define L_NOOBJ 0.5f
#define TPB 128
#define NWARP (TPB / 32)
#define CPW 32                    // cells per warp-tile
#define PRED_B (CPW * 120)        // 3840
#define TCLS_B (CPW * 80)         // 2560
#define TBOX_B (CPW * 16)         // 512
#define BUF_B (PRED_B + TCLS_B + TBOX_B)   // 6912
#define SMEM_BYTES (NWARP * 2 * BUF_B)     // 55296

__device__ double g_acc[4];      // cls, noobj(raw), reg(raw), containing
__device__ unsigned g_counter;   // zero-init; reset by last block each run

extern __shared__ __align__(16) char dsm[];

__device__ __forceinline__ bool loadMask(const void* maskv, int mode,
                                         int c, int ncell) {
    if (c >= ncell) return false;
    if (mode == 0)  return ((const int*)maskv)[c] != 0;
    if (mode == 1)  return ((const unsigned char*)maskv)[c] != 0;
    return ((const float*)maskv)[c] != 0.0f;
}

__device__ __forceinline__ void stageTile(
    const float* __restrict__ pred, const float* __restrict__ tcls,
    const float* __restrict__ tbox,
    int cellBase, int lane, int ncell, unsigned sbuf)
{
    long long rem = (long long)ncell - cellBase;    // cells remaining
    // pred: 240 chunks
    {
        const char* g = (const char*)(pred + (size_t)cellBase * 30);
        long long bytes = rem * 120;
#pragma unroll
        for (int k = 0; k < 8; k++) {
            int ch = lane + 32 * k;
            if (ch < PRED_B / 16 && (long long)ch * 16 < bytes)
                asm volatile("cp.async.cg.shared.global [%0], [%1], 16;\n"
                             :: "r"(sbuf + (unsigned)(ch * 16)),
                                "l"(g + ch * 16));
        }
    }
    // tcls: 160 chunks
    {
        const char* g = (const char*)(tcls + (size_t)cellBase * 20);
        long long bytes = rem * 80;
#pragma unroll
        for (int k = 0; k < 5; k++) {
            int ch = lane + 32 * k;
            if ((long long)ch * 16 < bytes)
                asm volatile("cp.async.cg.shared.global [%0], [%1], 16;\n"
                             :: "r"(sbuf + PRED_B + (unsigned)(ch * 16)),
                                "l"(g + ch * 16));
        }
    }
    // tbox: 32 chunks
    {
        const char* g = (const char*)(tbox + (size_t)cellBase * 4);
        long long bytes = rem * 16;
        int ch = lane;
        if ((long long)ch * 16 < bytes)
            asm volatile("cp.async.cg.shared.global [%0], [%1], 16;\n"
                         :: "r"(sbuf + PRED_B + TCLS_B + (unsigned)(ch * 16)),
                            "l"(g + ch * 16));
    }
    asm volatile("cp.async.commit_group;\n");
}

__device__ __forceinline__ void computeTile(
    const char* buf, int cellBase, int lane, int ncell, bool m,
    float& s_cls, float& s_noobj, float& s_reg, float& s_cont)
{
    const int c = cellBase + lane;
    if (c >= ncell) return;

    const float2* mp2 = (const float2*)(buf + lane * 120);   // 8B aligned

    if (!m) {
        float cf0 = mp2[2].x;    // pred float idx 4
        float cf1 = mp2[4].y;    // pred float idx 9
        s_noobj += cf0 * cf0 + cf1 * cf1;
        return;
    }

    float pv[10];
#pragma unroll
    for (int j = 0; j < 5; j++) {
        float2 v = mp2[j];
        pv[2 * j]     = v.x;
        pv[2 * j + 1] = v.y;
    }

    // ---- class loss (all smem) ----
    {
        const float4* tc4 = (const float4*)(buf + PRED_B + lane * 80);
        const float2* mc2 = (const float2*)(buf + lane * 120 + 40);
        float cls = 0.f;
#pragma unroll
        for (int j = 0; j < 5; j++) {
            float4 t = tc4[j];
            float2 a = mc2[2 * j];
            float2 b = mc2[2 * j + 1];
            float d0 = t.x - a.x;
            float d1 = t.y - a.y;
            float d2 = t.z - b.x;
            float d3 = t.w - b.y;
            cls += d0 * d0 + d1 * d1 + d2 * d2 + d3 * d3;
        }
        s_cls += cls;
    }

    // ---- IoU of the two pred boxes vs target ----
    float4 tb = *(const float4*)(buf + PRED_B + TCLS_B + lane * 16);
    float t_cx = tb.x * S_GRID_INV;
    float t_cy = tb.y * S_GRID_INV;
    float t_x1 = t_cx - 0.5f * tb.z;
    float t_y1 = t_cy - 0.5f * tb.w;
    float t_x2 = t_cx + 0.5f * tb.z;
    float t_y2 = t_cy + 0.5f * tb.w;
    float area_t = (t_x2 - t_x1) * (t_y2 - t_y1);

    float iou[2];
#pragma unroll
    for (int b = 0; b < 2; b++) {
        float px = pv[5 * b + 0] * S_GRID_INV;
        float py = pv[5 * b + 1] * S_GRID_INV;
        float pw = pv[5 * b + 2];
        float ph = pv[5 * b + 3];
        float p_x1 = px - 0.5f * pw;
        float p_y1 = py - 0.5f * ph;
        float p_x2 = px + 0.5f * pw;
        float p_y2 = py + 0.5f * ph;
        float lt_x = fmaxf(t_x1, p_x1);
        float lt_y = fmaxf(t_y1, p_y1);
        float rb_x = fminf(t_x2, p_x2);
        float rb_y = fminf(t_y2, p_y2);
        float w = fmaxf(rb_x - lt_x, 0.0f);
        float h = fmaxf(rb_y - lt_y, 0.0f);
        float inter = w * h;
        float area_p = (p_x2 - p_x1) * (p_y2 - p_y1);
        iou[b] = inter / (area_t + area_p - inter);
    }

    bool sel = iou[1] > iou[0];     // first max wins on tie
    float best_iou = sel ? iou[1] : iou[0];
    float bb_x = sel ? pv[5] : pv[0];
    float bb_y = sel ? pv[6] : pv[1];
    float bb_w = sel ? pv[7] : pv[2];
    float bb_h = sel ? pv[8] : pv[3];
    float bb_c = sel ? pv[9] : pv[4];

    float dx = bb_x - tb.x;
    float dy = bb_y - tb.y;
    float sw = sqrtf(bb_w) - sqrtf(tb.z);
    float sh = sqrtf(bb_h) - sqrtf(tb.w);
    s_reg += dx * dx + dy * dy + sw * sw + sh * sh;

    float dc = best_iou - bb_c;
    s_cont += dc * dc;
}

__global__ void __launch_bounds__(TPB, 4) yolo_fused_kernel(
    const float* __restrict__ pred,
    const float* __restrict__ tbox,
    const float* __restrict__ tcls,
    const void* __restrict__ maskv,
    int ncell, int n_batch, int ntiles, float* __restrict__ out)
{
    __shared__ float sm[4][NWARP];
    __shared__ bool s_last;

    const int tid  = threadIdx.x;
    const int warp = tid >> 5;
    const int lane = tid & 31;
    const int gw = blockIdx.x * NWARP + warp;
    const int wstride = gridDim.x * NWARP;

    char* wb = dsm + warp * (2 * BUF_B);
    unsigned sb[2];
    sb[0] = (unsigned)__cvta_generic_to_shared(wb);
    sb[1] = (unsigned)__cvta_generic_to_shared(wb + BUF_B);

    // ---- mask dtype detection: warp-local ballot over first 32 words ----
    int mode;
    {
        unsigned w0 = ((const unsigned*)maskv)[lane];
        bool gt1 = w0 > 1u;
        bool bad = ((w0 & 0xFFu) > 1u) | (((w0 >> 8) & 0xFFu) > 1u) |
                   (((w0 >> 16) & 0xFFu) > 1u) | ((w0 >> 24) > 1u);
        unsigned bg = __ballot_sync(0xFFFFFFFFu, gt1);
        unsigned bb = __ballot_sync(0xFFFFFFFFu, bad);
        mode = (bg == 0) ? 0 : (bb ? 2 : 1);
    }

    float s_cls = 0.f, s_noobj = 0.f, s_reg = 0.f, s_cont = 0.f;

    // ---- warp-level double-buffered pipeline over grid-strided tiles ----
    int t = gw;
    if (t < ntiles) {
        stageTile(pred, tcls, tbox, t * CPW, lane, ncell, sb[0]);
        bool mCur = loadMask(maskv, mode, t * CPW + lane, ncell);

        int tn = t + wstride;
        int sel = 0;
        while (true) {
            bool hasN = tn < ntiles;
            bool mNext = false;
            if (hasN) {
                stageTile(pred, tcls, tbox, tn * CPW, lane, ncell, sb[sel ^ 1]);
                mNext = loadMask(maskv, mode, tn * CPW + lane, ncell);
            }
            if (hasN) { asm volatile("cp.async.wait_group 1;\n" ::: "memory"); }
            else      { asm volatile("cp.async.wait_group 0;\n" ::: "memory"); }
            __syncwarp();

            computeTile(sel ? wb + BUF_B : wb, t * CPW, lane, ncell, mCur,
                        s_cls, s_noobj, s_reg, s_cont);

            if (!hasN) break;
            t = tn; tn += wstride; mCur = mNext; sel ^= 1;
            __syncwarp();   // all lanes done with old buffer before restage
        }
    }

    // ---- warp reduction, then block reduction ----
#pragma unroll
    for (int off = 16; off; off >>= 1) {
        s_cls   += __shfl_down_sync(0xFFFFFFFFu, s_cls,   off);
        s_noobj += __shfl_down_sync(0xFFFFFFFFu, s_noobj, off);
        s_reg   += __shfl_down_sync(0xFFFFFFFFu, s_reg,   off);
        s_cont  += __shfl_down_sync(0xFFFFFFFFu, s_cont,  off);
    }
    if (lane == 0) {
        sm[0][warp] = s_cls;
        sm[1][warp] = s_noobj;
        sm[2][warp] = s_reg;
        sm[3][warp] = s_cont;
    }
    __syncthreads();

    if (tid == 0) {
        float a0 = 0.f, a1 = 0.f, a2 = 0.f, a3 = 0.f;
#pragma unroll
        for (int w = 0; w < NWARP; w++) {
            a0 += sm[0][w];
            a1 += sm[1][w];
            a2 += sm[2][w];
            a3 += sm[3][w];
        }
        atomicAdd(&g_acc[0], (double)a0);
        atomicAdd(&g_acc[1], (double)a1);
        atomicAdd(&g_acc[2], (double)a2);
        atomicAdd(&g_acc[3], (double)a3);

        __threadfence();
        unsigned old = atomicAdd(&g_counter, 1u);
        s_last = (old == gridDim.x - 1);
    }
    __syncthreads();

    // ---- last block: finalize + reset persistent state ----
    if (s_last && tid == 0) {
        double cls   = atomicAdd(&g_acc[0], 0.0);
        double noobj = (double)L_NOOBJ * atomicAdd(&g_acc[1], 0.0);
        double reg   = (double)L_COORD * atomicAdd(&g_acc[2], 0.0);
        double cont  = atomicAdd(&g_acc[3], 0.0);
        double total = (cls + noobj + reg + cont) / (double)n_batch;
        out[0] = (float)total;
        out[1] = (float)reg;
        out[2] = (float)cont;
        out[3] = (float)noobj;
        out[4] = (float)cls;
        g_acc[0] = 0.0; g_acc[1] = 0.0; g_acc[2] = 0.0; g_acc[3] = 0.0;
        __threadfence();
        g_counter = 0u;
    }
}

extern "C" void kernel_launch(void* const* d_in, const int* in_sizes, int n_in,
                              void* d_out, int out_size) {
    // Identify inputs by element count: pred = 30n, tcls = 20n, tbox = 4n, mask = n
    const void* ptrs[4] = {d_in[0], d_in[1], d_in[2], d_in[3]};
    long long sz[4] = {in_sizes[0], in_sizes[1], in_sizes[2], in_sizes[3]};

    int im = 0;
    for (int i = 1; i < 4; i++) if (sz[i] < sz[im]) im = i;
    long long n = sz[im];

    const float* pred = nullptr;
    const float* tbox = nullptr;
    const float* tcls = nullptr;
    const void*  hmask = ptrs[im];
    for (int i = 0; i < 4; i++) {
        if (i == im) continue;
        if (sz[i] == 30 * n) pred = (const float*)ptrs[i];
        else if (sz[i] == 20 * n) tcls = (const float*)ptrs[i];
        else if (sz[i] == 4 * n) tbox = (const float*)ptrs[i];
    }

    int ncell = (int)n;                   // 802816
    int n_batch = ncell / (14 * 14);      // 4096
    int ntiles = (ncell + CPW - 1) / CPW; // 25088

    cudaFuncSetAttribute(yolo_fused_kernel,
                         cudaFuncAttributeMaxDynamicSharedMemorySize,
                         SMEM_BYTES);

    int dev = 0, nsm = 148;
    cudaGetDevice(&dev);
    cudaDeviceGetAttribute(&nsm, cudaDevAttrMultiProcessorCount, dev);

    int blocks = nsm * 4;                 // 4 blocks/SM (smem-limited)
    int maxBlocks = (ntiles + NWARP - 1) / NWARP;
    if (blocks > maxBlocks) blocks = maxBlocks;

    yolo_fused_kernel<<<blocks, TPB, SMEM_BYTES>>>(
        pred, tbox, tcls, hmask, ncell, n_batch, ntiles, (float*)d_out);
}

// round 15
// speedup vs baseline: 1.3467x; 1.3467x over previous
#include <cuda_runtime.h>
#include <math.h>

// YOLO loss — fused single launch. Warp-level double-buffered cp.async
// pipeline (R13) + register-prefetched tbox. tcls streamed direct.
// Outputs 5 f32: total, reg, containing, noobj, cls.

#define S_GRID_INV (1.0f / 14.0f)
#define L_COORD 5.0f
#define L_NOOBJ 0.5f
#define TPB 128
#define NWARP (TPB / 32)
#define CPW 32                   // cells per warp-tile
#define TILE_FL (CPW * 30)       // 960 floats = 3840 B
#define TILE_CH (CPW * 120 / 16) // 240 x 16B chunks

__device__ double g_acc[4];      // cls, noobj(raw), reg(raw), containing
__device__ unsigned g_counter;   // zero-init; reset by last block each run

__device__ __forceinline__ bool loadMask(const void* maskv, int mode,
                                         int c, int ncell) {
    if (c >= ncell) return false;
    if (mode == 0)  return ((const int*)maskv)[c] != 0;
    if (mode == 1)  return ((const unsigned char*)maskv)[c] != 0;
    return ((const float*)maskv)[c] != 0.0f;
}

__device__ __forceinline__ float4 loadTbox(const float* tbox, int c,
                                           int ncell, bool m) {
    if (m && c < ncell) return __ldcs(((const float4*)tbox) + c);
    return make_float4(0.f, 0.f, 0.f, 0.f);
}

__device__ __forceinline__ void stageTile(const float* __restrict__ pred,
                                          int cellBase, int lane, int ncell,
                                          unsigned sbuf) {
    const char* gp = (const char*)(pred + (size_t)cellBase * 30);
    long long bytes = ((long long)ncell - cellBase) * 120;
#pragma unroll
    for (int k = 0; k < 8; k++) {
        int ch = lane + 32 * k;
        long long off = (long long)ch * 16;
        if (ch < TILE_CH && off < bytes)
            asm volatile("cp.async.cg.shared.global [%0], [%1], 16;\n"
                         :: "r"(sbuf + (unsigned)(ch * 16)), "l"(gp + off));
    }
    asm volatile("cp.async.commit_group;\n");
}

__device__ __forceinline__ void computeTile(
    const float* buf, int cellBase, int lane, int ncell, bool m, float4 tb,
    const float* __restrict__ tcls,
    float& s_cls, float& s_noobj, float& s_reg, float& s_cont)
{
    const int c = cellBase + lane;
    if (c >= ncell) return;

    const float2* mp2 = (const float2*)(buf + lane * 30);   // 8B aligned

    if (!m) {
        float cf0 = mp2[2].x;    // pred float idx 4
        float cf1 = mp2[4].y;    // pred float idx 9
        s_noobj += cf0 * cf0 + cf1 * cf1;
        return;
    }

    float pv[10];
#pragma unroll
    for (int j = 0; j < 5; j++) {
        float2 v = mp2[j];
        pv[2 * j]     = v.x;
        pv[2 * j + 1] = v.y;
    }

    // ---- class loss: tcls streamed direct, pred classes from smem ----
    {
        const float4* tc4 = (const float4*)tcls + (size_t)c * 5;
        const float2* mc2 = (const float2*)(buf + lane * 30 + 10);
        float cls = 0.f;
#pragma unroll
        for (int j = 0; j < 5; j++) {
            float4 t = __ldcs(tc4 + j);
            float2 a = mc2[2 * j];
            float2 b = mc2[2 * j + 1];
            float d0 = t.x - a.x;
            float d1 = t.y - a.y;
            float d2 = t.z - b.x;
            float d3 = t.w - b.y;
            cls += d0 * d0 + d1 * d1 + d2 * d2 + d3 * d3;
        }
        s_cls += cls;
    }

    // ---- IoU of the two pred boxes vs target (tb prefetched in regs) ----
    float t_cx = tb.x * S_GRID_INV;
    float t_cy = tb.y * S_GRID_INV;
    float t_x1 = t_cx - 0.5f * tb.z;
    float t_y1 = t_cy - 0.5f * tb.w;
    float t_x2 = t_cx + 0.5f * tb.z;
    float t_y2 = t_cy + 0.5f * tb.w;
    float area_t = (t_x2 - t_x1) * (t_y2 - t_y1);

    float iou[2];
#pragma unroll
    for (int b = 0; b < 2; b++) {
        float px = pv[5 * b + 0] * S_GRID_INV;
        float py = pv[5 * b + 1] * S_GRID_INV;
        float pw = pv[5 * b + 2];
        float ph = pv[5 * b + 3];
        float p_x1 = px - 0.5f * pw;
        float p_y1 = py - 0.5f * ph;
        float p_x2 = px + 0.5f * pw;
        float p_y2 = py + 0.5f * ph;
        float lt_x = fmaxf(t_x1, p_x1);
        float lt_y = fmaxf(t_y1, p_y1);
        float rb_x = fminf(t_x2, p_x2);
        float rb_y = fminf(t_y2, p_y2);
        float w = fmaxf(rb_x - lt_x, 0.0f);
        float h = fmaxf(rb_y - lt_y, 0.0f);
        float inter = w * h;
        float area_p = (p_x2 - p_x1) * (p_y2 - p_y1);
        iou[b] = inter / (area_t + area_p - inter);
    }

    bool sel = iou[1] > iou[0];    // first max wins on tie
    float best_iou = sel ? iou[1] : iou[0];
    float bb_x = sel ? pv[5] : pv[0];
    float bb_y = sel ? pv[6] : pv[1];
    float bb_w = sel ? pv[7] : pv[2];
    float bb_h = sel ? pv[8] : pv[3];
    float bb_c = sel ? pv[9] : pv[4];

    float dx = bb_x - tb.x;
    float dy = bb_y - tb.y;
    float sw = sqrtf(bb_w) - sqrtf(tb.z);
    float sh = sqrtf(bb_h) - sqrtf(tb.w);
    s_reg += dx * dx + dy * dy + sw * sw + sh * sh;

    float dc = best_iou - bb_c;
    s_cont += dc * dc;
}

__global__ void __launch_bounds__(TPB, 7) yolo_fused_kernel(
    const float* __restrict__ pred,
    const float* __restrict__ tbox,
    const float* __restrict__ tcls,
    const void* __restrict__ maskv,
    int ncell, int n_batch, int ntiles, float* __restrict__ out)
{
    __shared__ float sp[NWARP][2][TILE_FL];   // 30.7 KB
    __shared__ float sm[4][NWARP];
    __shared__ bool s_last;

    const int tid  = threadIdx.x;
    const int warp = tid >> 5;
    const int lane = tid & 31;
    const int gw = blockIdx.x * NWARP + warp;        // global warp id
    const int wstride = gridDim.x * NWARP;

    unsigned sb[2];
    sb[0] = (unsigned)__cvta_generic_to_shared(&sp[warp][0][0]);
    sb[1] = (unsigned)__cvta_generic_to_shared(&sp[warp][1][0]);

    // ---- mask dtype detection: warp-local ballot over first 32 words ----
    int mode;
    {
        unsigned w0 = ((const unsigned*)maskv)[lane];
        bool gt1 = w0 > 1u;
        bool bad = ((w0 & 0xFFu) > 1u) | (((w0 >> 8) & 0xFFu) > 1u) |
                   (((w0 >> 16) & 0xFFu) > 1u) | ((w0 >> 24) > 1u);
        unsigned bg = __ballot_sync(0xFFFFFFFFu, gt1);
        unsigned bb = __ballot_sync(0xFFFFFFFFu, bad);
        mode = (bg == 0) ? 0 : (bb ? 2 : 1);
    }

    float s_cls = 0.f, s_noobj = 0.f, s_reg = 0.f, s_cont = 0.f;

    // ---- warp-level double-buffered pipeline over grid-strided tiles ----
    int t = gw;
    if (t < ntiles) {
        stageTile(pred, t * CPW, lane, ncell, sb[0]);
        bool mCur = loadMask(maskv, mode, t * CPW + lane, ncell);
        float4 tbCur = loadTbox(tbox, t * CPW + lane, ncell, mCur);

        int tn = t + wstride;
        int sel = 0;
        while (true) {
            bool hasN = tn < ntiles;
            bool mNext = false;
            float4 tbNext = make_float4(0.f, 0.f, 0.f, 0.f);
            if (hasN) {
                stageTile(pred, tn * CPW, lane, ncell, sb[sel ^ 1]);
                mNext = loadMask(maskv, mode, tn * CPW + lane, ncell);
                tbNext = loadTbox(tbox, tn * CPW + lane, ncell, mNext);
            }
            if (hasN) { asm volatile("cp.async.wait_group 1;\n" ::: "memory"); }
            else      { asm volatile("cp.async.wait_group 0;\n" ::: "memory"); }
            __syncwarp();

            computeTile(&sp[warp][sel][0], t * CPW, lane, ncell, mCur, tbCur,
                        tcls, s_cls, s_noobj, s_reg, s_cont);

            if (!hasN) break;
            t = tn; tn += wstride; mCur = mNext; tbCur = tbNext; sel ^= 1;
            __syncwarp();   // all lanes done with old buffer before restage
        }
    }

    // ---- warp reduction, then block reduction ----
#pragma unroll
    for (int off = 16; off; off >>= 1) {
        s_cls   += __shfl_down_sync(0xFFFFFFFFu, s_cls,   off);
        s_noobj += __shfl_down_sync(0xFFFFFFFFu, s_noobj, off);
        s_reg   += __shfl_down_sync(0xFFFFFFFFu, s_reg,   off);
        s_cont  += __shfl_down_sync(0xFFFFFFFFu, s_cont,  off);
    }
    if (lane == 0) {
        sm[0][warp] = s_cls;
        sm[1][warp] = s_noobj;
        sm[2][warp] = s_reg;
        sm[3][warp] = s_cont;
    }
    __syncthreads();

    if (tid == 0) {
        float a0 = 0.f, a1 = 0.f, a2 = 0.f, a3 = 0.f;
#pragma unroll
        for (int w = 0; w < NWARP; w++) {
            a0 += sm[0][w];
            a1 += sm[1][w];
            a2 += sm[2][w];
            a3 += sm[3][w];
        }
        atomicAdd(&g_acc[0], (double)a0);
        atomicAdd(&g_acc[1], (double)a1);
        atomicAdd(&g_acc[2], (double)a2);
        atomicAdd(&g_acc[3], (double)a3);

        __threadfence();
        unsigned old = atomicAdd(&g_counter, 1u);
        s_last = (old == gridDim.x - 1);
    }
    __syncthreads();

    // ---- last block: finalize + reset persistent state ----
    if (s_last && tid == 0) {
        double cls   = atomicAdd(&g_acc[0], 0.0);
        double noobj = (double)L_NOOBJ * atomicAdd(&g_acc[1], 0.0);
        double reg   = (double)L_COORD * atomicAdd(&g_acc[2], 0.0);
        double cont  = atomicAdd(&g_acc[3], 0.0);
        double total = (cls + noobj + reg + cont) / (double)n_batch;
        out[0] = (float)total;
        out[1] = (float)reg;
        out[2] = (float)cont;
        out[3] = (float)noobj;
        out[4] = (float)cls;
        g_acc[0] = 0.0; g_acc[1] = 0.0; g_acc[2] = 0.0; g_acc[3] = 0.0;
        __threadfence();
        g_counter = 0u;
    }
}

extern "C" void kernel_launch(void* const* d_in, const int* in_sizes, int n_in,
                              void* d_out, int out_size) {
    // Identify inputs by element count: pred = 30n, tcls = 20n, tbox = 4n, mask = n
    const void* ptrs[4] = {d_in[0], d_in[1], d_in[2], d_in[3]};
    long long sz[4] = {in_sizes[0], in_sizes[1], in_sizes[2], in_sizes[3]};

    int im = 0;
    for (int i = 1; i < 4; i++) if (sz[i] < sz[im]) im = i;
    long long n = sz[im];

    const float* pred = nullptr;
    const float* tbox = nullptr;
    const float* tcls = nullptr;
    const void*  hmask = ptrs[im];
    for (int i = 0; i < 4; i++) {
        if (i == im) continue;
        if (sz[i] == 30 * n) pred = (const float*)ptrs[i];
        else if (sz[i] == 20 * n) tcls = (const float*)ptrs[i];
        else if (sz[i] == 4 * n) tbox = (const float*)ptrs[i];
    }

    int ncell = (int)n;                   // 802816
    int n_batch = ncell / (14 * 14);      // 4096
    int ntiles = (ncell + CPW - 1) / CPW; // 25088

    int dev = 0, nsm = 148;
    cudaGetDevice(&dev);
    cudaDeviceGetAttribute(&nsm, cudaDevAttrMultiProcessorCount, dev);

    int blocks = nsm * 7;                 // 7 blocks/SM, grid-strided tiles
    int maxBlocks = (ntiles + NWARP - 1) / NWARP;
    if (blocks > maxBlocks) blocks = maxBlocks;

    yolo_fused_kernel<<<blocks, TPB>>>(pred, tbox, tcls, hmask,
                                       ncell, n_batch, ntiles, (float*)d_out);
}